// round 5
// baseline (speedup 1.0000x reference)
#include <cuda_runtime.h>

typedef unsigned long long u64;
typedef unsigned int u32;

#define SEQ   256
#define LAB   128
#define BATCH 8192
#define NF    8
#define HD    64
#define NW    8            // warps per block
#define NTHR  (NW * 32)
#define RPW   8            // rows per warp
#define TB    (NW * RPW)   // 64
#define NBLK  (BATCH / TB) // 128
#define HPAD  66           // h row stride in u64 (528B: kills out-proj row conflicts)

// ---- SMEM layout (float offsets) ----
// wih2 [4][3][32][4]  : 2k-interleaved, dup-unit quads {w[2k2][u0],w[2k2][u1],w[2k2+1][u0],w[2k2+1][u1]}
// whh2 [32][3][32][4]
// bias [4][64]        : r, z, n_i, n_h  (pair (b[u0],b[u1]) loads as u64)
// wout [64][4][2]     : (Wout[o4][k], Wout[o4+4][k]) pairs
// h2   [NW][RPW][HPAD] u64 (duplicated values)
// xs2  [NW][2][64]     u64 (duplicated staged inputs)
#define OFF_WIH2 0
#define OFF_WHH2 1536
#define OFF_BIAS 13824
#define OFF_WOUT 14080
#define OFF_BOUT 14592
#define OFF_H2   14608
#define OFF_XS2  (OFF_H2 + NW*RPW*HPAD*2)
#define SMEM_FLOATS (OFF_XS2 + NW*2*64*2)
#define SMEM_BYTES  (SMEM_FLOATS * 4)

__device__ __forceinline__ u64 f2fma(u64 a, u64 b, u64 c) {
    u64 d; asm("fma.rn.f32x2 %0,%1,%2,%3;" : "=l"(d) : "l"(a), "l"(b), "l"(c)); return d;
}
__device__ __forceinline__ u64 dup2(float v) {
    u64 d; asm("mov.b64 %0,{%1,%1};" : "=l"(d) : "f"(v)); return d;
}
__device__ __forceinline__ void unpk(u64 v, float& a, float& b) {
    asm("mov.b64 {%0,%1},%2;" : "=f"(a), "=f"(b) : "l"(v));
}
__device__ __forceinline__ void lds2(u64& a, u64& b, u32 ad) {
    asm volatile("ld.shared.v2.u64 {%0,%1},[%2];" : "=l"(a), "=l"(b) : "r"(ad));
}
__device__ __forceinline__ u64 lds1(u32 ad) {
    u64 a; asm volatile("ld.shared.b64 %0,[%1];" : "=l"(a) : "r"(ad)); return a;
}
__device__ __forceinline__ void sts2(u32 ad, u64 a, u64 b) {
    asm volatile("st.shared.v2.u64 [%0],{%1,%2};" :: "r"(ad), "l"(a), "l"(b) : "memory");
}
__device__ __forceinline__ void sts1(u32 ad, u64 a) {
    asm volatile("st.shared.b64 [%0],%1;" :: "r"(ad), "l"(a) : "memory");
}
__device__ __forceinline__ float tanha(float x) {
    float y; asm("tanh.approx.f32 %0,%1;" : "=f"(y) : "f"(x)); return y;
}
__device__ __forceinline__ float sigt(float x) { return fmaf(0.5f, tanha(0.5f * x), 0.5f); }

// One GRU step: this warp's 8 rows x 64 units. Warp-private.
__device__ __forceinline__ void gru_step(
    u32 wih_a, u32 whh_a,
    u64 br, u64 bz, u64 bni, u64 bnh,
    u32 xs_a, u32 h_a, int lane2)
{
    u64 ar[RPW], az[RPW], an[RPW], ah[RPW];
    #pragma unroll
    for (int r = 0; r < RPW; r++) { ar[r] = br; az[r] = bz; an[r] = bni; ah[r] = bnh; }

    // ---- input GEMM: 4 blocks of 2k ----
    #pragma unroll
    for (int k2 = 0; k2 < NF / 2; k2++) {
        u64 wr0, wr1, wz0, wz1, wn0, wn1;
        u32 wa = wih_a + (u32)(k2 * 1536) + (u32)(lane2 * 8);
        lds2(wr0, wr1, wa);
        lds2(wz0, wz1, wa + 512);
        lds2(wn0, wn1, wa + 1024);
        #pragma unroll
        for (int r = 0; r < RPW; r++) {
            u64 x0, x1; lds2(x0, x1, xs_a + (u32)((r * 8 + k2 * 2) * 8));
            ar[r] = f2fma(x0, wr0, ar[r]); az[r] = f2fma(x0, wz0, az[r]); an[r] = f2fma(x0, wn0, an[r]);
            ar[r] = f2fma(x1, wr1, ar[r]); az[r] = f2fma(x1, wz1, az[r]); an[r] = f2fma(x1, wn1, an[r]);
        }
    }

    // ---- recurrent GEMM: 32 blocks of 2k ----
    #pragma unroll 4
    for (int k2 = 0; k2 < HD / 2; k2++) {
        u64 wr0, wr1, wz0, wz1, wn0, wn1;
        u32 wa = whh_a + (u32)(k2 * 1536) + (u32)(lane2 * 8);
        lds2(wr0, wr1, wa);
        lds2(wz0, wz1, wa + 512);
        lds2(wn0, wn1, wa + 1024);
        #pragma unroll
        for (int r = 0; r < RPW; r++) {
            u64 h0, h1; lds2(h0, h1, h_a + (u32)((r * HPAD + k2 * 2) * 8));
            ar[r] = f2fma(h0, wr0, ar[r]); az[r] = f2fma(h0, wz0, az[r]); ah[r] = f2fma(h0, wn0, ah[r]);
            ar[r] = f2fma(h1, wr1, ar[r]); az[r] = f2fma(h1, wz1, az[r]); ah[r] = f2fma(h1, wn1, ah[r]);
        }
    }
    __syncwarp();   // all lanes done reading h before any lane rewrites it

    // ---- gates + h update (lane owns units lane2, lane2+1) ----
    #pragma unroll
    for (int r = 0; r < RPW; r++) {
        float r0, r1, z0, z1, i0, i1, g0, g1;
        unpk(ar[r], r0, r1); unpk(az[r], z0, z1);
        unpk(an[r], i0, i1); unpk(ah[r], g0, g1);
        float R0 = sigt(r0), R1 = sigt(r1);
        float Z0 = sigt(z0), Z1 = sigt(z1);
        float N0 = tanha(fmaf(R0, g0, i0));
        float N1 = tanha(fmaf(R1, g1, i1));
        u32 ha = h_a + (u32)((r * HPAD + lane2) * 8);
        u64 o0, o1; lds2(o0, o1, ha);
        float ho0, t0, ho1, t1;
        unpk(o0, ho0, t0); unpk(o1, ho1, t1);
        float hn0 = fmaf(Z0, ho0 - N0, N0);
        float hn1 = fmaf(Z1, ho1 - N1, N1);
        sts2(ha, dup2(hn0), dup2(hn1));
    }
    __syncwarp();
}

__device__ __forceinline__ void load_weights(
    float* smem,
    const float* __restrict__ Wih, const float* __restrict__ Whh,
    const float* __restrict__ bih, const float* __restrict__ bhh, int tid)
{
    for (int i = tid; i < NF * 3 * HD; i += NTHR) {      // 1536
        int j = i & 3, u2 = (i >> 2) & 31, g = (i >> 7) % 3, k2 = i / 384;
        int u = u2 * 2 + (j & 1), k = k2 * 2 + (j >> 1);
        smem[OFF_WIH2 + i] = Wih[(g * HD + u) * NF + k];
    }
    for (int i = tid; i < HD * 3 * HD; i += NTHR) {      // 12288
        int j = i & 3, u2 = (i >> 2) & 31, g = (i >> 7) % 3, k2 = i / 384;
        int u = u2 * 2 + (j & 1), k = k2 * 2 + (j >> 1);
        smem[OFF_WHH2 + i] = Whh[(g * HD + u) * HD + k];
    }
    if (tid < HD) {
        smem[OFF_BIAS + tid]       = bih[tid]       + bhh[tid];
        smem[OFF_BIAS + 64 + tid]  = bih[64 + tid]  + bhh[64 + tid];
        smem[OFF_BIAS + 128 + tid] = bih[128 + tid];
        smem[OFF_BIAS + 192 + tid] = bhh[128 + tid];
    }
}

__global__ __launch_bounds__(NTHR, 1)
void seq2seq_gru_kernel(const float* __restrict__ x,
                        const float* __restrict__ xy,
                        const float* __restrict__ eWih, const float* __restrict__ eWhh,
                        const float* __restrict__ ebih, const float* __restrict__ ebhh,
                        const float* __restrict__ dWih, const float* __restrict__ dWhh,
                        const float* __restrict__ dbih, const float* __restrict__ dbhh,
                        const float* __restrict__ Wout, const float* __restrict__ bout,
                        float* __restrict__ out)
{
    extern __shared__ float smem[];
    const int tid   = threadIdx.x;
    const int lane  = tid & 31;
    const int warp  = tid >> 5;
    const int lane2 = lane * 2;
    const int rowb  = blockIdx.x * TB + warp * RPW;

    const u32 sbase  = (u32)__cvta_generic_to_shared(smem);
    const u32 wih_a  = sbase + OFF_WIH2 * 4;
    const u32 whh_a  = sbase + OFF_WHH2 * 4;
    const u32 bias_a = sbase + OFF_BIAS * 4;
    const u32 wout_a = sbase + OFF_WOUT * 4;
    const u32 bout_a = sbase + OFF_BOUT * 4;
    const u32 h_a    = sbase + (OFF_H2 + warp * RPW * HPAD * 2) * 4;
    const u32 xs_a   = sbase + (OFF_XS2 + warp * 256) * 4;   // two 512B buffers

    // ---- encoder weights + out-proj + zero h ----
    load_weights(smem, eWih, eWhh, ebih, ebhh, tid);
    for (int i = tid; i < HD * 8; i += NTHR) {               // wout pairs
        int k = i >> 3, rem = i & 7, o4 = rem >> 1, s = rem & 1;
        smem[OFF_WOUT + i] = Wout[(o4 + 4 * s) * HD + k];
    }
    if (tid < 8) { int o4 = tid >> 1, s = tid & 1; smem[OFF_BOUT + tid] = bout[o4 + 4 * s]; }
    for (int i = tid; i < NW * RPW * HPAD * 2; i += NTHR) smem[OFF_H2 + i] = 0.0f;
    __syncthreads();

    u64 br  = lds1(bias_a + lane2 * 4);
    u64 bz  = lds1(bias_a + (64 + lane2) * 4);
    u64 bni = lds1(bias_a + (128 + lane2) * 4);
    u64 bnh = lds1(bias_a + (192 + lane2) * 4);

    // =========================== ENCODER ===========================
    {
        float2 rx = ((const float2*)x)[((size_t)0 * BATCH + rowb) * 4 + lane];
        sts2(xs_a + lane * 16, dup2(rx.x), dup2(rx.y));      // buffer 0 (dup'd)
        __syncwarp();
        for (int t = 0; t < SEQ; t++) {
            if (t + 1 < SEQ)
                rx = ((const float2*)x)[((size_t)(t + 1) * BATCH + rowb) * 4 + lane];
            gru_step(wih_a, whh_a, br, bz, bni, bnh,
                     xs_a + (t & 1) * 512, h_a, lane2);
            if (t + 1 < SEQ)
                sts2(xs_a + ((t + 1) & 1) * 512 + lane * 16, dup2(rx.x), dup2(rx.y));
            __syncwarp();
        }
    }

    // ---- phase swap: decoder weights ----
    __syncthreads();
    load_weights(smem, dWih, dWhh, dbih, dbhh, tid);
    __syncthreads();

    br  = lds1(bias_a + lane2 * 4);
    bz  = lds1(bias_a + (64 + lane2) * 4);
    bni = lds1(bias_a + (128 + lane2) * 4);
    bnh = lds1(bias_a + (192 + lane2) * 4);

    // =========================== DECODER ===========================
    // All 32 lanes: lane = orow*4 + oo4; lane produces outputs (oo4, oo4+4) of row orow.
    const int orow = lane >> 2;        // 0..7  (8 rows per warp)
    const int oo4  = lane & 3;
    const u64 bop  = lds1(bout_a + oo4 * 8);

    {
        float2 rx = ((const float2*)xy)[(size_t)rowb * 4 + lane];
        sts2(xs_a + lane * 16, dup2(rx.x), dup2(rx.y));      // buffer 0
        __syncwarp();

        for (int t = 0; t < LAB; t++) {
            gru_step(wih_a, whh_a, br, bz, bni, bnh,
                     xs_a + (t & 1) * 512, h_a, lane2);

            // out = h_new @ Wout^T + bout ; lane produces (o4, o4+4) of row orow
            u64 acc = bop;
            const u32 ha = h_a + (u32)(orow * HPAD * 8);
            const u32 wa = wout_a + (u32)(oo4 * 8);
            #pragma unroll 8
            for (int k2 = 0; k2 < 32; k2++) {
                u64 hk0, hk1; lds2(hk0, hk1, ha + k2 * 16);   // dup'd h[2k2], h[2k2+1]
                acc = f2fma(hk0, lds1(wa + (2 * k2)     * 32), acc);
                acc = f2fma(hk1, lds1(wa + (2 * k2 + 1) * 32), acc);
            }
            float oa, ob; unpk(acc, oa, ob);

            float* og = out + ((size_t)t * BATCH + rowb + orow) * NF;
            og[oo4]     = oa;
            og[oo4 + 4] = ob;

            if (t + 1 < LAB) {
                u32 nb = xs_a + ((t + 1) & 1) * 512;
                sts1(nb + (u32)((orow * 8 + oo4)     * 8), dup2(oa));
                sts1(nb + (u32)((orow * 8 + oo4 + 4) * 8), dup2(ob));
            }
            __syncwarp();
        }
    }
}

extern "C" void kernel_launch(void* const* d_in, const int* in_sizes, int n_in,
                              void* d_out, int out_size) {
    (void)in_sizes; (void)n_in; (void)out_size;
    const float* x     = (const float*)d_in[0];
    const float* xy    = (const float*)d_in[1];
    const float* eWih  = (const float*)d_in[2];
    const float* eWhh  = (const float*)d_in[3];
    const float* ebih  = (const float*)d_in[4];
    const float* ebhh  = (const float*)d_in[5];
    const float* dWih  = (const float*)d_in[6];
    const float* dWhh  = (const float*)d_in[7];
    const float* dbih  = (const float*)d_in[8];
    const float* dbhh  = (const float*)d_in[9];
    const float* Wout  = (const float*)d_in[10];
    const float* bout  = (const float*)d_in[11];
    float* out = (float*)d_out;

    cudaFuncSetAttribute(seq2seq_gru_kernel,
                         cudaFuncAttributeMaxDynamicSharedMemorySize, SMEM_BYTES);
    seq2seq_gru_kernel<<<NBLK, NTHR, SMEM_BYTES>>>(
        x, xy, eWih, eWhh, ebih, ebhh, dWih, dWhh, dbih, dbhh, Wout, bout, out);
}

// round 6
// speedup vs baseline: 1.0108x; 1.0108x over previous
#include <cuda_runtime.h>

typedef unsigned long long u64;
typedef unsigned int u32;

#define SEQ   256
#define LAB   128
#define BATCH 8192
#define NF    8
#define HD    64
#define NW    8            // warps per block
#define NTHR  (NW * 32)
#define RPW   8            // rows per warp
#define TB    (NW * RPW)   // 64
#define NBLK  (BATCH / TB) // 128
#define HPAD  66           // h row stride in u64 (528B -> conflict-free out-proj)

// ---- SMEM layout (float offsets) ----
// wih2 [4 k2][3 g][32 lanes][4]  quads {w[k0][u0],w[k0][u1],w[k1][u0],w[k1][u1]}
// whh2 [32 k2][3 g][32 lanes][4]
// bias [4][64] : r, z, n_i, n_h
// wout [64][4][2] : (Wout[o4][k], Wout[o4+4][k]) pairs
// h2   [NW][RPW][HPAD] u64 (dup'd)   xs2 [NW][2][64] u64 (dup'd)
#define OFF_WIH2 0
#define OFF_WHH2 1536
#define OFF_BIAS 13824
#define OFF_WOUT 14080
#define OFF_BOUT 14592
#define OFF_H2   14608
#define OFF_XS2  (OFF_H2 + NW*RPW*HPAD*2)
#define SMEM_FLOATS (OFF_XS2 + NW*2*64*2)
#define SMEM_BYTES  (SMEM_FLOATS * 4)

__device__ __forceinline__ u64 f2fma(u64 a, u64 b, u64 c) {
    u64 d; asm("fma.rn.f32x2 %0,%1,%2,%3;" : "=l"(d) : "l"(a), "l"(b), "l"(c)); return d;
}
__device__ __forceinline__ u64 dup2(float v) {
    u64 d; asm("mov.b64 %0,{%1,%1};" : "=l"(d) : "f"(v)); return d;
}
__device__ __forceinline__ void unpk(u64 v, float& a, float& b) {
    asm("mov.b64 {%0,%1},%2;" : "=f"(a), "=f"(b) : "l"(v));
}
__device__ __forceinline__ float tanha(float x) {
    float y; asm("tanh.approx.f32 %0,%1;" : "=f"(y) : "f"(x)); return y;
}
__device__ __forceinline__ float sigt(float x) { return fmaf(0.5f, tanha(0.5f * x), 0.5f); }

// One GRU step: this warp's 8 rows x 64 units. Warp-private.
// All loads are plain C++ derefs -> ptxas schedules/batches them freely.
__device__ __forceinline__ void gru_step(
    const float* __restrict__ wih,   // quad layout, 384 floats per k2
    const float* __restrict__ whh,
    u64 br, u64 bz, u64 bni, u64 bnh,
    const u64* __restrict__ xs,      // dup'd [r*8 + f]
    u64* __restrict__ h2,            // dup'd [r*HPAD + k]
    float hr[RPW][2],                // register copy of this lane's own units
    int lane2)
{
    u64 ar[RPW], az[RPW], an[RPW], ah[RPW];
    #pragma unroll
    for (int r = 0; r < RPW; r++) { ar[r] = br; az[r] = bz; an[r] = bni; ah[r] = bnh; }

    // ---- input GEMM: 4 blocks of 2k ----
    #pragma unroll
    for (int k2 = 0; k2 < NF / 2; k2++) {
        const ulonglong2* wq = (const ulonglong2*)(wih + k2 * 384 + lane2 * 2);
        ulonglong2 wr = wq[0];     // gate r : (k0 pair, k1 pair)
        ulonglong2 wz = wq[32];    // +128 floats
        ulonglong2 wn = wq[64];    // +256 floats
        #pragma unroll
        for (int r = 0; r < RPW; r++) {
            ulonglong2 xv = *(const ulonglong2*)(xs + r * 8 + k2 * 2);
            ar[r] = f2fma(xv.x, wr.x, ar[r]); az[r] = f2fma(xv.x, wz.x, az[r]); an[r] = f2fma(xv.x, wn.x, an[r]);
            ar[r] = f2fma(xv.y, wr.y, ar[r]); az[r] = f2fma(xv.y, wz.y, az[r]); an[r] = f2fma(xv.y, wn.y, an[r]);
        }
    }

    // ---- recurrent GEMM: 32 blocks of 2k ----
    #pragma unroll 4
    for (int k2 = 0; k2 < HD / 2; k2++) {
        const ulonglong2* wq = (const ulonglong2*)(whh + k2 * 384 + lane2 * 2);
        ulonglong2 wr = wq[0];
        ulonglong2 wz = wq[32];
        ulonglong2 wn = wq[64];
        #pragma unroll
        for (int r = 0; r < RPW; r++) {
            ulonglong2 hv = *(const ulonglong2*)(h2 + r * HPAD + k2 * 2);
            ar[r] = f2fma(hv.x, wr.x, ar[r]); az[r] = f2fma(hv.x, wz.x, az[r]); ah[r] = f2fma(hv.x, wn.x, ah[r]);
            ar[r] = f2fma(hv.y, wr.y, ar[r]); az[r] = f2fma(hv.y, wz.y, az[r]); ah[r] = f2fma(hv.y, wn.y, ah[r]);
        }
    }
    __syncwarp();   // all lanes done reading h before rewrites

    // ---- gates + h update (lane owns units lane2, lane2+1; old h in regs) ----
    #pragma unroll
    for (int r = 0; r < RPW; r++) {
        float r0, r1, z0, z1, i0, i1, g0, g1;
        unpk(ar[r], r0, r1); unpk(az[r], z0, z1);
        unpk(an[r], i0, i1); unpk(ah[r], g0, g1);
        float R0 = sigt(r0), R1 = sigt(r1);
        float Z0 = sigt(z0), Z1 = sigt(z1);
        float N0 = tanha(fmaf(R0, g0, i0));
        float N1 = tanha(fmaf(R1, g1, i1));
        float hn0 = fmaf(Z0, hr[r][0] - N0, N0);
        float hn1 = fmaf(Z1, hr[r][1] - N1, N1);
        hr[r][0] = hn0; hr[r][1] = hn1;
        ulonglong2 st; st.x = dup2(hn0); st.y = dup2(hn1);
        *(ulonglong2*)(h2 + r * HPAD + lane2) = st;
    }
    __syncwarp();
}

__device__ __forceinline__ void load_weights(
    float* smem,
    const float* __restrict__ Wih, const float* __restrict__ Whh,
    const float* __restrict__ bih, const float* __restrict__ bhh, int tid)
{
    for (int i = tid; i < NF * 3 * HD; i += NTHR) {      // 1536
        int j = i & 3, u2 = (i >> 2) & 31, g = (i >> 7) % 3, k2 = i / 384;
        int u = u2 * 2 + (j & 1), k = k2 * 2 + (j >> 1);
        smem[OFF_WIH2 + i] = Wih[(g * HD + u) * NF + k];
    }
    for (int i = tid; i < HD * 3 * HD; i += NTHR) {      // 12288
        int j = i & 3, u2 = (i >> 2) & 31, g = (i >> 7) % 3, k2 = i / 384;
        int u = u2 * 2 + (j & 1), k = k2 * 2 + (j >> 1);
        smem[OFF_WHH2 + i] = Whh[(g * HD + u) * HD + k];
    }
    if (tid < HD) {
        smem[OFF_BIAS + tid]       = bih[tid]       + bhh[tid];
        smem[OFF_BIAS + 64 + tid]  = bih[64 + tid]  + bhh[64 + tid];
        smem[OFF_BIAS + 128 + tid] = bih[128 + tid];
        smem[OFF_BIAS + 192 + tid] = bhh[128 + tid];
    }
}

__global__ __launch_bounds__(NTHR, 1)
void seq2seq_gru_kernel(const float* __restrict__ x,
                        const float* __restrict__ xy,
                        const float* __restrict__ eWih, const float* __restrict__ eWhh,
                        const float* __restrict__ ebih, const float* __restrict__ ebhh,
                        const float* __restrict__ dWih, const float* __restrict__ dWhh,
                        const float* __restrict__ dbih, const float* __restrict__ dbhh,
                        const float* __restrict__ Wout, const float* __restrict__ bout,
                        float* __restrict__ out)
{
    extern __shared__ float smem[];
    const int tid   = threadIdx.x;
    const int lane  = tid & 31;
    const int warp  = tid >> 5;
    const int lane2 = lane * 2;
    const int rowb  = blockIdx.x * TB + warp * RPW;

    const float* wih  = smem + OFF_WIH2;
    const float* whh  = smem + OFF_WHH2;
    const float* bias = smem + OFF_BIAS;
    u64* h2  = (u64*)(smem + OFF_H2) + warp * RPW * HPAD;
    u64* xsw = (u64*)(smem + OFF_XS2) + warp * 128;      // two 64-u64 buffers

    // ---- encoder weights + out-proj + zero h ----
    load_weights(smem, eWih, eWhh, ebih, ebhh, tid);
    for (int i = tid; i < HD * 8; i += NTHR) {           // wout pairs
        int k = i >> 3, rem = i & 7, o4 = rem >> 1, s = rem & 1;
        smem[OFF_WOUT + i] = Wout[(o4 + 4 * s) * HD + k];
    }
    if (tid < 8) { int o4 = tid >> 1, s = tid & 1; smem[OFF_BOUT + tid] = bout[o4 + 4 * s]; }
    for (int i = tid; i < NW * RPW * HPAD * 2; i += NTHR) smem[OFF_H2 + i] = 0.0f;
    __syncthreads();

    float hr[RPW][2];
    #pragma unroll
    for (int r = 0; r < RPW; r++) { hr[r][0] = 0.0f; hr[r][1] = 0.0f; }

    u64 br  = *(const u64*)(bias + lane2);
    u64 bz  = *(const u64*)(bias + 64 + lane2);
    u64 bni = *(const u64*)(bias + 128 + lane2);
    u64 bnh = *(const u64*)(bias + 192 + lane2);

    // =========================== ENCODER ===========================
    {
        float2 rx = ((const float2*)x)[((size_t)0 * BATCH + rowb) * 4 + lane];
        { ulonglong2 st; st.x = dup2(rx.x); st.y = dup2(rx.y);
          *(ulonglong2*)(xsw + lane * 2) = st; }
        __syncwarp();
        for (int t = 0; t < SEQ; t++) {
            if (t + 1 < SEQ)
                rx = ((const float2*)x)[((size_t)(t + 1) * BATCH + rowb) * 4 + lane];
            gru_step(wih, whh, br, bz, bni, bnh,
                     xsw + (t & 1) * 64, h2, hr, lane2);
            if (t + 1 < SEQ) {
                ulonglong2 st; st.x = dup2(rx.x); st.y = dup2(rx.y);
                *(ulonglong2*)(xsw + ((t + 1) & 1) * 64 + lane * 2) = st;
            }
            __syncwarp();
        }
    }

    // ---- phase swap: decoder weights ----
    __syncthreads();
    load_weights(smem, dWih, dWhh, dbih, dbhh, tid);
    __syncthreads();

    br  = *(const u64*)(bias + lane2);
    bz  = *(const u64*)(bias + 64 + lane2);
    bni = *(const u64*)(bias + 128 + lane2);
    bnh = *(const u64*)(bias + 192 + lane2);

    // =========================== DECODER ===========================
    // All 32 lanes: lane = orow*4 + oo4; lane produces outputs (oo4, oo4+4) of row orow.
    const int orow = lane >> 2;        // 0..7
    const int oo4  = lane & 3;
    const u64* woutq = (const u64*)(smem + OFF_WOUT) + oo4;   // stride 4 u64 per k
    const u64  bop   = ((const u64*)(smem + OFF_BOUT))[oo4];

    {
        float2 rx = ((const float2*)xy)[(size_t)rowb * 4 + lane];
        { ulonglong2 st; st.x = dup2(rx.x); st.y = dup2(rx.y);
          *(ulonglong2*)(xsw + lane * 2) = st; }
        __syncwarp();

        for (int t = 0; t < LAB; t++) {
            gru_step(wih, whh, br, bz, bni, bnh,
                     xsw + (t & 1) * 64, h2, hr, lane2);

            // out = h_new @ Wout^T + bout ; lane -> (o4, o4+4) of row orow
            u64 acc = bop;
            const u64* hp = h2 + orow * HPAD;
            #pragma unroll 8
            for (int k2 = 0; k2 < 32; k2++) {
                ulonglong2 hk = *(const ulonglong2*)(hp + k2 * 2);  // dup'd h[2k2], h[2k2+1]
                acc = f2fma(hk.x, woutq[(2 * k2)     * 4], acc);
                acc = f2fma(hk.y, woutq[(2 * k2 + 1) * 4], acc);
            }
            float oa, ob; unpk(acc, oa, ob);

            float* og = out + ((size_t)t * BATCH + rowb + orow) * NF;
            og[oo4]     = oa;
            og[oo4 + 4] = ob;

            if (t + 1 < LAB) {
                u64* nb = xsw + ((t + 1) & 1) * 64;
                nb[orow * 8 + oo4]     = dup2(oa);
                nb[orow * 8 + oo4 + 4] = dup2(ob);
            }
            __syncwarp();
        }
    }
}

extern "C" void kernel_launch(void* const* d_in, const int* in_sizes, int n_in,
                              void* d_out, int out_size) {
    (void)in_sizes; (void)n_in; (void)out_size;
    const float* x     = (const float*)d_in[0];
    const float* xy    = (const float*)d_in[1];
    const float* eWih  = (const float*)d_in[2];
    const float* eWhh  = (const float*)d_in[3];
    const float* ebih  = (const float*)d_in[4];
    const float* ebhh  = (const float*)d_in[5];
    const float* dWih  = (const float*)d_in[6];
    const float* dWhh  = (const float*)d_in[7];
    const float* dbih  = (const float*)d_in[8];
    const float* dbhh  = (const float*)d_in[9];
    const float* Wout  = (const float*)d_in[10];
    const float* bout  = (const float*)d_in[11];
    float* out = (float*)d_out;

    cudaFuncSetAttribute(seq2seq_gru_kernel,
                         cudaFuncAttributeMaxDynamicSharedMemorySize, SMEM_BYTES);
    seq2seq_gru_kernel<<<NBLK, NTHR, SMEM_BYTES>>>(
        x, xy, eWih, eWhh, ebih, ebhh, dWih, dWhh, dbih, dbhh, Wout, bout, out);
}